// round 16
// baseline (speedup 1.0000x reference)
#include <cuda_runtime.h>
#include <cuda_bf16.h>
#include <mma.h>
#include <math.h>

using namespace nvcuda;

#define NB 16
#define NN 8192
#define NC 256
#define NH 4
#define NK 64
#define NCHUNK 8

// Scratch (__device__ globals; no allocations allowed)
static __device__ float g_part[NCHUNK * NB * NC * NK];          // partials
static __device__ __nv_bfloat16 g_ef2h[NN * NK], g_ef2l[NN * NK];           // [n][k]
static __device__ __nv_bfloat16 g_skph[NB * NC * NK], g_skpl[NB * NC * NK]; // [b][h][k][d]
static __device__ __nv_bfloat16 g_vph[NB * NH * 64 * 64], g_vpl[NB * NH * 64 * 64]; // [b][h][m][k]

__device__ __forceinline__ void split2(float v, __nv_bfloat16& hi, __nv_bfloat16& lo) {
    hi = __float2bfloat16_rn(v);
    lo = __float2bfloat16_rn(v - __bfloat162float(hi));
}

// mma.sync m16n8k16 row.col bf16 -> f32, D += A*B
__device__ __forceinline__ void mma16816(float* c, const unsigned* a, const unsigned* b) {
    asm volatile(
        "mma.sync.aligned.m16n8k16.row.col.f32.bf16.bf16.f32 "
        "{%0,%1,%2,%3}, {%4,%5,%6,%7}, {%8,%9}, {%0,%1,%2,%3};"
        : "+f"(c[0]), "+f"(c[1]), "+f"(c[2]), "+f"(c[3])
        : "r"(a[0]), "r"(a[1]), "r"(a[2]), "r"(a[3]), "r"(b[0]), "r"(b[1]));
}

__device__ __forceinline__ void ldsm_x4(unsigned* r, const void* p) {
    unsigned a = (unsigned)__cvta_generic_to_shared(p);
    asm volatile("ldmatrix.sync.aligned.m8n8.x4.shared.b16 {%0,%1,%2,%3}, [%4];"
        : "=r"(r[0]), "=r"(r[1]), "=r"(r[2]), "=r"(r[3]) : "r"(a));
}

__device__ __forceinline__ unsigned pack_bf16(__nv_bfloat16 lo, __nv_bfloat16 hi) {
    __nv_bfloat162 p = __halves2bfloat162(lo, hi);   // .x = low half
    return *(unsigned*)&p;
}

__device__ __forceinline__ void cp_async16(void* smem, const void* gmem) {
    unsigned s = (unsigned)__cvta_generic_to_shared(smem);
    asm volatile("cp.async.cg.shared.global [%0], [%1], 16;" :: "r"(s), "l"(gmem));
}
__device__ __forceinline__ void cp_commit() { asm volatile("cp.async.commit_group;"); }
__device__ __forceinline__ void cp_wait0()  { asm volatile("cp.async.wait_group 0;" ::: "memory"); }
__device__ __forceinline__ void cp_wait1()  { asm volatile("cp.async.wait_group 1;" ::: "memory"); }

// ---------------------------------------------------------------------------
// Prep: split EF2 into bf16 hi/lo (vectorized, 4 elems/thread)
// ---------------------------------------------------------------------------
__global__ void k_prep_ef2(const float* __restrict__ ef2) {
    int i = (blockIdx.x * 256 + threadIdx.x) * 4;
    float4 v = *(const float4*)&ef2[i];
    __nv_bfloat16 h0, l0, h1, l1, h2, l2, h3, l3;
    split2(v.x, h0, l0); split2(v.y, h1, l1);
    split2(v.z, h2, l2); split2(v.w, h3, l3);
    *(uint2*)&g_ef2h[i] = make_uint2(pack_bf16(h0, h1), pack_bf16(h2, h3));
    *(uint2*)&g_ef2l[i] = make_uint2(pack_bf16(l0, l1), pack_bf16(l2, l3));
}

// global_vp (fp32, tiny), fused split + transpose epilogue:
// g_vph[bh][m][k=d1] = split(sum_n1 gf[b,n1,h*64+d1]*EF1[n1,m])
__global__ void k_gvp(const float* __restrict__ gf, const float* __restrict__ ef1) {
    int bh = blockIdx.x, b = bh >> 2, h = bh & 3;
    __shared__ float gs[64][64];
    __shared__ float es[64][64];
    int t = threadIdx.x;
    for (int i = t; i < 4096; i += 256) {
        int r = i >> 6, c = i & 63;
        gs[r][c] = gf[(b * 64 + r) * 256 + h * 64 + c];
        es[r][c] = ef1[i];
    }
    __syncthreads();
    int d0 = (t >> 4) << 2, m0 = (t & 15) << 2;
    float acc[4][4] = {};
    for (int n1 = 0; n1 < 64; n1++) {
        float4 a = *(const float4*)&gs[n1][d0];
        float4 v = *(const float4*)&es[n1][m0];
        float av[4] = {a.x, a.y, a.z, a.w};
        float bv[4] = {v.x, v.y, v.z, v.w};
        #pragma unroll
        for (int i = 0; i < 4; i++)
            #pragma unroll
            for (int j = 0; j < 4; j++)
                acc[i][j] += av[i] * bv[j];
    }
    size_t base = (size_t)bh * 4096;
    #pragma unroll
    for (int i = 0; i < 4; i++)
        #pragma unroll
        for (int j = 0; j < 4; j++) {
            __nv_bfloat16 hi, lo;
            split2(acc[i][j], hi, lo);
            size_t o = base + (size_t)(m0 + j) * 64 + (d0 + i);  // [m][k]
            g_vph[o] = hi;
            g_vpl[o] = lo;
        }
}

// ---------------------------------------------------------------------------
// skip_kp partials (wmma bf16x3).
// 32-row supersteps. skip now arrives via cp.async into fp32 staging
// (issued TWO supersteps ahead, wait_group 1) -- the prefetch is structural,
// ptxas cannot sink it. Split reads LDS (29 cyc) instead of a DRAM-latency
// register. ef2 cp.async one superstep ahead. One barrier per superstep.
// smem 52 KB -> occupancy 4 (208 KB/SM), 512 CTAs in one wave.
// part[chunk][b][c][k] = sum_{n in chunk} skip[b,n,c]*EF2[n,k]
// ---------------------------------------------------------------------------
__global__ void __launch_bounds__(256) k_skp(const float* __restrict__ skip) {
    extern __shared__ char sm[];
    __nv_bfloat16* ash = (__nv_bfloat16*)sm;            // [2][32][72]
    __nv_bfloat16* asl = ash + 2 * 32 * 72;
    __nv_bfloat16* bsh = asl + 2 * 32 * 72;
    __nv_bfloat16* bsl = bsh + 2 * 32 * 72;
    float* fst = (float*)(bsl + 2 * 32 * 72);           // [2][32][64] fp32 skip staging

    int chunk = blockIdx.x, ct = blockIdx.y, b = blockIdx.z;
    int t = threadIdx.x, w = t >> 5;

    wmma::fragment<wmma::accumulator, 16, 16, 16, float> acc[2];
    wmma::fill_fragment(acc[0], 0.f);
    wmma::fill_fragment(acc[1], 0.f);
    int c0 = (w >> 1) * 16;
    int kc = (w & 1) * 32;

    int lr = t >> 4, lc4 = (t & 15) * 4;                 // staging rows lr, lr+16
    int er = (t & 127) >> 3, ek8 = (t & 7) * 8;          // ef2: rows er, er+16
    bool hiload = (t < 128);

    size_t sbase = ((size_t)b * NN + chunk * 1024) * NC + ct * 64 + lc4;
    size_t ebase = (size_t)(chunk * 1024 + er) * 64 + ek8;
    const __nv_bfloat16* esrc = hiload ? g_ef2h : g_ef2l;
    __nv_bfloat16* bdst = hiload ? bsh : bsl;

    // ---- prologue ----
    // group A: skip ss=0 -> fst[0], ef2 ss=0 -> b[0]
    #pragma unroll
    for (int j = 0; j < 2; j++) {
        cp_async16(&fst[(j * 16 + lr) * 64 + lc4], &skip[sbase + (size_t)(j * 16 + lr) * NC]);
        cp_async16(&bdst[(j * 16 + er) * 72 + ek8], &esrc[ebase + (size_t)(j * 16) * 64]);
    }
    cp_commit();
    // group B: skip ss=1 -> fst[1]
    #pragma unroll
    for (int j = 0; j < 2; j++)
        cp_async16(&fst[2048 + (j * 16 + lr) * 64 + lc4],
                   &skip[sbase + (size_t)(32 + j * 16 + lr) * NC]);
    cp_commit();
    cp_wait1();                     // group A complete (fst[0], ef2[0])
    #pragma unroll
    for (int j = 0; j < 2; j++) {   // split fst[0] -> bf16 stage 0
        float4 v = *(const float4*)&fst[(j * 16 + lr) * 64 + lc4];
        __nv_bfloat16 hx, lx, hy, ly, hz, lz, hw, lw;
        split2(v.x, hx, lx); split2(v.y, hy, ly);
        split2(v.z, hz, lz); split2(v.w, hw, lw);
        int row = j * 16 + lr;
        *(uint2*)&ash[row * 72 + lc4] = make_uint2(pack_bf16(hx, hy), pack_bf16(hz, hw));
        *(uint2*)&asl[row * 72 + lc4] = make_uint2(pack_bf16(lx, ly), pack_bf16(lz, lw));
    }
    __syncthreads();

    for (int ss = 0; ss < 32; ss++) {
        int cur = ss & 1, nxt = cur ^ 1;

        // ef2 for ss+1 (one ahead) -- commit FIRST
        if (ss < 31) {
            #pragma unroll
            for (int j = 0; j < 2; j++)
                cp_async16(&bdst[(nxt * 32 + j * 16 + er) * 72 + ek8],
                           &esrc[ebase + (size_t)((ss + 1) * 32 + j * 16) * 64]);
            cp_commit();
        }
        // skip for ss+2 (two ahead) into fst[cur] (dead) -- commit SECOND (newest)
        if (ss < 30) {
            #pragma unroll
            for (int j = 0; j < 2; j++)
                cp_async16(&fst[cur * 2048 + (j * 16 + lr) * 64 + lc4],
                           &skip[sbase + (size_t)((ss + 2) * 32 + j * 16 + lr) * NC]);
            cp_commit();
        }

        // MMA block on stage cur: 2 sub-steps of 16 rows
        #pragma unroll
        for (int sub = 0; sub < 2; sub++) {
            wmma::fragment<wmma::matrix_a, 16, 16, 16, __nv_bfloat16, wmma::col_major> ah, al;
            wmma::load_matrix_sync(ah, &ash[(cur * 32 + sub * 16) * 72 + c0], 72);
            wmma::load_matrix_sync(al, &asl[(cur * 32 + sub * 16) * 72 + c0], 72);
            #pragma unroll
            for (int kt = 0; kt < 2; kt++) {
                wmma::fragment<wmma::matrix_b, 16, 16, 16, __nv_bfloat16, wmma::row_major> bh, bl;
                wmma::load_matrix_sync(bh, &bsh[(cur * 32 + sub * 16) * 72 + kc + kt * 16], 72);
                wmma::load_matrix_sync(bl, &bsl[(cur * 32 + sub * 16) * 72 + kc + kt * 16], 72);
                wmma::mma_sync(acc[kt], ah, bh, acc[kt]);
                wmma::mma_sync(acc[kt], ah, bl, acc[kt]);
                wmma::mma_sync(acc[kt], al, bh, acc[kt]);
            }
        }

        // complete ef2(ss+1) + fst(ss+1); leave skip(ss+2) in flight
        if (ss < 30) cp_wait1(); else cp_wait0();

        // split fst[nxt] (data for ss+1) -> bf16 stage nxt
        if (ss < 31) {
            #pragma unroll
            for (int j = 0; j < 2; j++) {
                float4 v = *(const float4*)&fst[nxt * 2048 + (j * 16 + lr) * 64 + lc4];
                __nv_bfloat16 hx, lx, hy, ly, hz, lz, hw, lw;
                split2(v.x, hx, lx); split2(v.y, hy, ly);
                split2(v.z, hz, lz); split2(v.w, hw, lw);
                int row = nxt * 32 + j * 16 + lr;
                *(uint2*)&ash[row * 72 + lc4] = make_uint2(pack_bf16(hx, hy), pack_bf16(hz, hw));
                *(uint2*)&asl[row * 72 + lc4] = make_uint2(pack_bf16(lx, ly), pack_bf16(lz, lw));
            }
        }
        __syncthreads();
    }

    float* p = g_part + (((size_t)chunk * NB + b) * NC + ct * 64 + c0) * 64 + kc;
    wmma::store_matrix_sync(p, acc[0], 64, wmma::mem_row_major);
    wmma::store_matrix_sync(p + 16, acc[1], 64, wmma::mem_row_major);
}

// ---------------------------------------------------------------------------
// Reduce partials (fixed order), split + TRANSPOSE into g_skp[b][h][k][d].
// Vectorized: each thread reduces 4 consecutive k via float4.
// ---------------------------------------------------------------------------
__global__ void k_reduce() {
    int i = blockIdx.x * 256 + threadIdx.x;      // over 65536 float4 groups
    int idx = i * 4;
    float4 s = make_float4(0.f, 0.f, 0.f, 0.f);
    #pragma unroll
    for (int c = 0; c < NCHUNK; c++) {
        float4 p = *(const float4*)&g_part[(size_t)c * (NB * NC * NK) + idx];
        s.x += p.x; s.y += p.y; s.z += p.z; s.w += p.w;
    }
    int b = idx >> 14, rem = idx & 16383, c = rem >> 6, k0 = rem & 63;
    int h = c >> 6, d = c & 63;
    size_t ob = ((size_t)(b * NH + h) * 64) * 64 + d;   // + k*64
    float sv[4] = {s.x, s.y, s.z, s.w};
    #pragma unroll
    for (int j = 0; j < 4; j++) {
        __nv_bfloat16 hi, lo;
        split2(sv[j], hi, lo);
        size_t o = ob + (size_t)(k0 + j) * 64;
        g_skph[o] = hi;
        g_skpl[o] = lo;
    }
}

// ---------------------------------------------------------------------------
// Fused attention: q A-fragments direct from global, B via ldmatrix,
// register softmax + P-in-registers, DIRECT fragment->global writeback.
// 2 row-tiles (256 rows) per block; forced 2 CTAs/SM (regs 118).
// ---------------------------------------------------------------------------
#define TILES 2

__global__ void __launch_bounds__(256, 2) k_attn(
    const float* __restrict__ outq, const float* __restrict__ temp,
    float* __restrict__ x)
{
    extern __shared__ char smbuf[];
    __nv_bfloat16* sph = (__nv_bfloat16*)smbuf;          // 64x72  skpT [k][d]
    __nv_bfloat16* spl = sph + 64 * 72;
    __nv_bfloat16* vph = spl + 64 * 72;                  // 64x72  vpT  [m][k]
    __nv_bfloat16* vpl = vph + 64 * 72;

    int nt = blockIdx.x, h = blockIdx.y, b = blockIdx.z;
    int t = threadIdx.x, w = t >> 5, lane = t & 31;
    int gid = lane >> 2, tid = lane & 3;
    int r0 = w * 16;

    int brow = (lane & 7) + ((lane >> 4) << 3);
    int bcol8 = ((lane >> 3) & 1) * 8;

    {
        size_t base = (size_t)(b * NH + h) * 4096;
        for (int i = t; i < 512; i += 256) {
            int r = i >> 3, k8 = (i & 7) * 8;
            *(uint4*)&sph[r * 72 + k8] = *(const uint4*)&g_skph[base + r * 64 + k8];
            *(uint4*)&spl[r * 72 + k8] = *(const uint4*)&g_skpl[base + r * 64 + k8];
            *(uint4*)&vph[r * 72 + k8] = *(const uint4*)&g_vph[base + r * 64 + k8];
            *(uint4*)&vpl[r * 72 + k8] = *(const uint4*)&g_vpl[base + r * 64 + k8];
        }
    }
    float tempv = temp[h];
    __syncthreads();

    #pragma unroll 1
    for (int tile = 0; tile < TILES; tile++) {
        int rowbase = nt * (TILES * 128) + tile * 128 + r0 + gid;
        const float* qr0 = outq + ((size_t)b * NN + rowbase) * NC + h * 64;
        const float* qr8 = qr0 + 8 * NC;

        // ---- logits ----
        float acc[8][4];
        #pragma unroll
        for (int kb = 0; kb < 8; kb++)
            #pragma unroll
            for (int i = 0; i < 4; i++) acc[kb][i] = 0.f;

        #pragma unroll
        for (int dt = 0; dt < 4; dt++) {
            float2 v00 = *(const float2*)&qr0[dt * 16 + 2 * tid];
            float2 v10 = *(const float2*)&qr8[dt * 16 + 2 * tid];
            float2 v01 = *(const float2*)&qr0[dt * 16 + 2 * tid + 8];
            float2 v11 = *(const float2*)&qr8[dt * 16 + 2 * tid + 8];
            unsigned ah[4], al[4];
            {
                __nv_bfloat16 ha, la, hb, lb;
                split2(v00.x, ha, la); split2(v00.y, hb, lb);
                ah[0] = pack_bf16(ha, hb); al[0] = pack_bf16(la, lb);
                split2(v10.x, ha, la); split2(v10.y, hb, lb);
                ah[1] = pack_bf16(ha, hb); al[1] = pack_bf16(la, lb);
                split2(v01.x, ha, la); split2(v01.y, hb, lb);
                ah[2] = pack_bf16(ha, hb); al[2] = pack_bf16(la, lb);
                split2(v11.x, ha, la); split2(v11.y, hb, lb);
                ah[3] = pack_bf16(ha, hb); al[3] = pack_bf16(la, lb);
            }
            #pragma unroll
            for (int p = 0; p < 4; p++) {
                unsigned bh[4], bl[4];
                ldsm_x4(bh, &sph[(p * 16 + brow) * 72 + dt * 16 + bcol8]);
                ldsm_x4(bl, &spl[(p * 16 + brow) * 72 + dt * 16 + bcol8]);
                mma16816(acc[2 * p],     ah, bh);
                mma16816(acc[2 * p],     ah, bl);
                mma16816(acc[2 * p],     al, bh);
                mma16816(acc[2 * p + 1], ah, bh + 2);
                mma16816(acc[2 * p + 1], ah, bl + 2);
                mma16816(acc[2 * p + 1], al, bh + 2);
            }
        }

        // ---- softmax in registers ----
        #pragma unroll
        for (int kb = 0; kb < 8; kb++)
            #pragma unroll
            for (int i = 0; i < 4; i++) acc[kb][i] *= tempv;

        float mx0 = -1e30f, mx1 = -1e30f;
        #pragma unroll
        for (int kb = 0; kb < 8; kb++) {
            mx0 = fmaxf(mx0, fmaxf(acc[kb][0], acc[kb][1]));
            mx1 = fmaxf(mx1, fmaxf(acc[kb][2], acc[kb][3]));
        }
        mx0 = fmaxf(mx0, __shfl_xor_sync(0xffffffffu, mx0, 1));
        mx0 = fmaxf(mx0, __shfl_xor_sync(0xffffffffu, mx0, 2));
        mx1 = fmaxf(mx1, __shfl_xor_sync(0xffffffffu, mx1, 1));
        mx1 = fmaxf(mx1, __shfl_xor_sync(0xffffffffu, mx1, 2));

        float sum0 = 0.f, sum1 = 0.f;
        #pragma unroll
        for (int kb = 0; kb < 8; kb++) {
            acc[kb][0] = __expf(acc[kb][0] - mx0);
            acc[kb][1] = __expf(acc[kb][1] - mx0);
            acc[kb][2] = __expf(acc[kb][2] - mx1);
            acc[kb][3] = __expf(acc[kb][3] - mx1);
            sum0 += acc[kb][0] + acc[kb][1];
            sum1 += acc[kb][2] + acc[kb][3];
        }
        sum0 += __shfl_xor_sync(0xffffffffu, sum0, 1);
        sum0 += __shfl_xor_sync(0xffffffffu, sum0, 2);
        sum1 += __shfl_xor_sync(0xffffffffu, sum1, 1);
        sum1 += __shfl_xor_sync(0xffffffffu, sum1, 2);
        float inv0 = 1.f / sum0, inv1 = 1.f / sum1;

        // ---- pack P into bf16x3 A-fragments ----
        unsigned pah[4][4], pal[4][4];
        #pragma unroll
        for (int kt = 0; kt < 4; kt++) {
            #pragma unroll
            for (int half = 0; half < 2; half++) {
                int kb = 2 * kt + half;
                float p0 = acc[kb][0] * inv0, p1 = acc[kb][1] * inv0;
                float p2 = acc[kb][2] * inv1, p3 = acc[kb][3] * inv1;
                __nv_bfloat16 h0, l0, h1, l1, h2, l2, h3, l3;
                split2(p0, h0, l0); split2(p1, h1, l1);
                split2(p2, h2, l2); split2(p3, h3, l3);
                pah[kt][half * 2]     = pack_bf16(h0, h1);
                pah[kt][half * 2 + 1] = pack_bf16(h2, h3);
                pal[kt][half * 2]     = pack_bf16(l0, l1);
                pal[kt][half * 2 + 1] = pack_bf16(l2, l3);
            }
        }

        // ---- values ----
        float acc2[8][4];
        #pragma unroll
        for (int mb = 0; mb < 8; mb++)
            #pragma unroll
            for (int i = 0; i < 4; i++) acc2[mb][i] = 0.f;

        #pragma unroll
        for (int kt = 0; kt < 4; kt++) {
            #pragma unroll
            for (int p = 0; p < 4; p++) {
                unsigned bh[4], bl[4];
                ldsm_x4(bh, &vph[(p * 16 + brow) * 72 + kt * 16 + bcol8]);
                ldsm_x4(bl, &vpl[(p * 16 + brow) * 72 + kt * 16 + bcol8]);
                mma16816(acc2[2 * p],     pah[kt], bh);
                mma16816(acc2[2 * p],     pah[kt], bl);
                mma16816(acc2[2 * p],     pal[kt], bh);
                mma16816(acc2[2 * p + 1], pah[kt], bh + 2);
                mma16816(acc2[2 * p + 1], pah[kt], bl + 2);
                mma16816(acc2[2 * p + 1], pal[kt], bh + 2);
            }
        }

        // ---- direct writeback: x[b, m*(H*N) + h*N + n] ----
        // Fragment (mb,i) -> m = mb*8 + 2*tid + (i&1), n = rowbase + (i>>1)*8.
        // Per warp-store: 4 m-columns x 8 consecutive n = 4 full 32B sectors.
        {
            const size_t MS = (size_t)NH * NN;  // m stride
            float* od = x + (size_t)b * (NN * NC) + (size_t)h * NN + rowbase;
            #pragma unroll
            for (int mb = 0; mb < 8; mb++) {
                size_t m0 = (size_t)(mb * 8 + 2 * tid);
                od[m0 * MS]           = acc2[mb][0];
                od[(m0 + 1) * MS]     = acc2[mb][1];
                od[m0 * MS + 8]       = acc2[mb][2];
                od[(m0 + 1) * MS + 8] = acc2[mb][3];
            }
        }
    }
}

// ---------------------------------------------------------------------------
extern "C" void kernel_launch(void* const* d_in, const int* in_sizes, int n_in,
                              void* d_out, int out_size) {
    const float* skip = (const float*)d_in[0];
    const float* outq = (const float*)d_in[1];
    const float* gf   = (const float*)d_in[2];
    const float* ef1  = (const float*)d_in[3];
    const float* ef2  = (const float*)d_in[4];
    const float* temp = (const float*)d_in[5];
    float* x = (float*)d_out;

    const int ATTN_SMEM = 4 * 64 * 72 * 2;                    // 36864
    const int SKP_SMEM  = 4 * 2 * 32 * 72 * 2 + 2 * 32 * 64 * 4;  // 36864 + 16384 = 53248

    cudaFuncSetAttribute(k_attn, cudaFuncAttributeMaxDynamicSharedMemorySize, ATTN_SMEM);
    cudaFuncSetAttribute(k_skp,  cudaFuncAttributeMaxDynamicSharedMemorySize, SKP_SMEM);

    k_prep_ef2<<<(NN * NK) / 1024, 256>>>(ef2);
    k_gvp<<<NB * NH, 256>>>(gf, ef1);
    k_skp<<<dim3(NCHUNK, 4, NB), 256, SKP_SMEM>>>(skip);
    k_reduce<<<(NB * NC * NK) / 1024, 256>>>();
    k_attn<<<dim3(NN / (TILES * 128), NH, NB), 256, ATTN_SMEM>>>(outq, temp, x);
}

// round 17
// speedup vs baseline: 1.5156x; 1.5156x over previous
#include <cuda_runtime.h>
#include <cuda_bf16.h>
#include <mma.h>
#include <math.h>

using namespace nvcuda;

#define NB 16
#define NN 8192
#define NC 256
#define NH 4
#define NK 64
#define NCHUNK 8

// Scratch (__device__ globals; no allocations allowed)
static __device__ float g_part[NCHUNK * NB * NC * NK];          // partials
static __device__ __nv_bfloat16 g_ef2h[NN * NK], g_ef2l[NN * NK];           // [n][k]
static __device__ __nv_bfloat16 g_skph[NB * NC * NK], g_skpl[NB * NC * NK]; // [b][h][k][d]
static __device__ __nv_bfloat16 g_vph[NB * NH * 64 * 64], g_vpl[NB * NH * 64 * 64]; // [b][h][m][k]

__device__ __forceinline__ void split2(float v, __nv_bfloat16& hi, __nv_bfloat16& lo) {
    hi = __float2bfloat16_rn(v);
    lo = __float2bfloat16_rn(v - __bfloat162float(hi));
}

// mma.sync m16n8k16 row.col bf16 -> f32, D += A*B
__device__ __forceinline__ void mma16816(float* c, const unsigned* a, const unsigned* b) {
    asm volatile(
        "mma.sync.aligned.m16n8k16.row.col.f32.bf16.bf16.f32 "
        "{%0,%1,%2,%3}, {%4,%5,%6,%7}, {%8,%9}, {%0,%1,%2,%3};"
        : "+f"(c[0]), "+f"(c[1]), "+f"(c[2]), "+f"(c[3])
        : "r"(a[0]), "r"(a[1]), "r"(a[2]), "r"(a[3]), "r"(b[0]), "r"(b[1]));
}

__device__ __forceinline__ void ldsm_x4(unsigned* r, const void* p) {
    unsigned a = (unsigned)__cvta_generic_to_shared(p);
    asm volatile("ldmatrix.sync.aligned.m8n8.x4.shared.b16 {%0,%1,%2,%3}, [%4];"
        : "=r"(r[0]), "=r"(r[1]), "=r"(r[2]), "=r"(r[3]) : "r"(a));
}

__device__ __forceinline__ unsigned pack_bf16(__nv_bfloat16 lo, __nv_bfloat16 hi) {
    __nv_bfloat162 p = __halves2bfloat162(lo, hi);   // .x = low half
    return *(unsigned*)&p;
}

__device__ __forceinline__ void cp_async16(void* smem, const void* gmem) {
    unsigned s = (unsigned)__cvta_generic_to_shared(smem);
    asm volatile("cp.async.cg.shared.global [%0], [%1], 16;" :: "r"(s), "l"(gmem));
}
__device__ __forceinline__ void cp_commit() { asm volatile("cp.async.commit_group;"); }
__device__ __forceinline__ void cp_wait0()  { asm volatile("cp.async.wait_group 0;" ::: "memory"); }

// ---------------------------------------------------------------------------
// Prep: split EF2 into bf16 hi/lo (vectorized, 4 elems/thread)
// ---------------------------------------------------------------------------
__global__ void k_prep_ef2(const float* __restrict__ ef2) {
    int i = (blockIdx.x * 256 + threadIdx.x) * 4;
    float4 v = *(const float4*)&ef2[i];
    __nv_bfloat16 h0, l0, h1, l1, h2, l2, h3, l3;
    split2(v.x, h0, l0); split2(v.y, h1, l1);
    split2(v.z, h2, l2); split2(v.w, h3, l3);
    *(uint2*)&g_ef2h[i] = make_uint2(pack_bf16(h0, h1), pack_bf16(h2, h3));
    *(uint2*)&g_ef2l[i] = make_uint2(pack_bf16(l0, l1), pack_bf16(l2, l3));
}

// global_vp (fp32, tiny), fused split + transpose epilogue:
// g_vph[bh][m][k=d1] = split(sum_n1 gf[b,n1,h*64+d1]*EF1[n1,m])
__global__ void k_gvp(const float* __restrict__ gf, const float* __restrict__ ef1) {
    int bh = blockIdx.x, b = bh >> 2, h = bh & 3;
    __shared__ float gs[64][64];
    __shared__ float es[64][64];
    int t = threadIdx.x;
    for (int i = t; i < 4096; i += 256) {
        int r = i >> 6, c = i & 63;
        gs[r][c] = gf[(b * 64 + r) * 256 + h * 64 + c];
        es[r][c] = ef1[i];
    }
    __syncthreads();
    int d0 = (t >> 4) << 2, m0 = (t & 15) << 2;
    float acc[4][4] = {};
    for (int n1 = 0; n1 < 64; n1++) {
        float4 a = *(const float4*)&gs[n1][d0];
        float4 v = *(const float4*)&es[n1][m0];
        float av[4] = {a.x, a.y, a.z, a.w};
        float bv[4] = {v.x, v.y, v.z, v.w};
        #pragma unroll
        for (int i = 0; i < 4; i++)
            #pragma unroll
            for (int j = 0; j < 4; j++)
                acc[i][j] += av[i] * bv[j];
    }
    size_t base = (size_t)bh * 4096;
    #pragma unroll
    for (int i = 0; i < 4; i++)
        #pragma unroll
        for (int j = 0; j < 4; j++) {
            __nv_bfloat16 hi, lo;
            split2(acc[i][j], hi, lo);
            size_t o = base + (size_t)(m0 + j) * 64 + (d0 + i);  // [m][k]
            g_vph[o] = hi;
            g_vpl[o] = lo;
        }
}

// ---------------------------------------------------------------------------
// skip_kp partials (wmma bf16x3), m32n8k16 shape.
// Warp decomposition 2cg x 4kg (32c x 16k per warp): LDSM traffic per
// superstep 48KB -> 24KB (B-fragment redundancy 4x -> 2x, A amortized by m32).
// 32-row supersteps, 2-stage ping-pong (36.9 KB smem, occ 4, one wave).
// part[chunk][b][c][k] = sum_{n in chunk} skip[b,n,c]*EF2[n,k]
// ---------------------------------------------------------------------------
__global__ void __launch_bounds__(256) k_skp(const float* __restrict__ skip) {
    extern __shared__ char sm[];
    __nv_bfloat16* ash = (__nv_bfloat16*)sm;            // [2][32][72]
    __nv_bfloat16* asl = ash + 2 * 32 * 72;
    __nv_bfloat16* bsh = asl + 2 * 32 * 72;
    __nv_bfloat16* bsl = bsh + 2 * 32 * 72;

    int chunk = blockIdx.x, ct = blockIdx.y, b = blockIdx.z;
    int t = threadIdx.x, w = t >> 5;

    wmma::fragment<wmma::accumulator, 32, 8, 16, float> acc[2];
    wmma::fill_fragment(acc[0], 0.f);
    wmma::fill_fragment(acc[1], 0.f);
    int c0 = (w & 1) * 32;       // cg: 32 c-columns per warp
    int kc = (w >> 1) * 16;      // kg: 16 k-columns per warp

    int lr = t >> 4, lc4 = (t & 15) * 4;                 // skip loader: rows lr, lr+16
    int er = (t & 127) >> 3, ek8 = (t & 7) * 8;          // ef2: rows er, er+16
    bool hiload = (t < 128);

    size_t sbase = ((size_t)b * NN + chunk * 1024) * NC + ct * 64 + lc4;
    size_t ebase = (size_t)(chunk * 1024 + er) * 64 + ek8;
    const __nv_bfloat16* esrc = hiload ? g_ef2h : g_ef2l;
    __nv_bfloat16* bdst = hiload ? bsh : bsl;

    float4 v[2];

    // prologue: superstep 0 into stage 0
    #pragma unroll
    for (int j = 0; j < 2; j++) {
        cp_async16(&bdst[(j * 16 + er) * 72 + ek8], &esrc[ebase + (size_t)(j * 16) * 64]);
        v[j] = *(const float4*)&skip[sbase + (size_t)(j * 16 + lr) * NC];
    }
    cp_commit();
    #pragma unroll
    for (int j = 0; j < 2; j++) {
        __nv_bfloat16 hx, lx, hy, ly, hz, lz, hw, lw;
        split2(v[j].x, hx, lx); split2(v[j].y, hy, ly);
        split2(v[j].z, hz, lz); split2(v[j].w, hw, lw);
        int row = j * 16 + lr;
        *(uint2*)&ash[row * 72 + lc4] = make_uint2(pack_bf16(hx, hy), pack_bf16(hz, hw));
        *(uint2*)&asl[row * 72 + lc4] = make_uint2(pack_bf16(lx, ly), pack_bf16(lz, lw));
    }
    cp_wait0();
    __syncthreads();

    for (int ss = 0; ss < 32; ss++) {
        int cur = ss & 1, nxt = cur ^ 1;

        // issue next superstep's loads early (overlap with the MMA block)
        if (ss < 31) {
            size_t srow = sbase + (size_t)((ss + 1) * 32) * NC;
            size_t eoff = ebase + (size_t)((ss + 1) * 32) * 64;
            #pragma unroll
            for (int j = 0; j < 2; j++) {
                cp_async16(&bdst[(nxt * 32 + j * 16 + er) * 72 + ek8],
                           &esrc[eoff + (size_t)(j * 16) * 64]);
                v[j] = *(const float4*)&skip[srow + (size_t)(j * 16 + lr) * NC];
            }
            cp_commit();
        }

        // MMA block: 2 sub-steps of 16 rows; m32n8k16 fragments
        #pragma unroll
        for (int sub = 0; sub < 2; sub++) {
            wmma::fragment<wmma::matrix_a, 32, 8, 16, __nv_bfloat16, wmma::col_major> ah, al;
            wmma::load_matrix_sync(ah, &ash[(cur * 32 + sub * 16) * 72 + c0], 72);
            wmma::load_matrix_sync(al, &asl[(cur * 32 + sub * 16) * 72 + c0], 72);
            #pragma unroll
            for (int j = 0; j < 2; j++) {
                wmma::fragment<wmma::matrix_b, 32, 8, 16, __nv_bfloat16, wmma::row_major> bh, bl;
                wmma::load_matrix_sync(bh, &bsh[(cur * 32 + sub * 16) * 72 + kc + j * 8], 72);
                wmma::load_matrix_sync(bl, &bsl[(cur * 32 + sub * 16) * 72 + kc + j * 8], 72);
                wmma::mma_sync(acc[j], ah, bh, acc[j]);
                wmma::mma_sync(acc[j], ah, bl, acc[j]);
                wmma::mma_sync(acc[j], al, bh, acc[j]);
            }
        }

        if (ss < 31) {
            #pragma unroll
            for (int j = 0; j < 2; j++) {
                __nv_bfloat16 hx, lx, hy, ly, hz, lz, hw, lw;
                split2(v[j].x, hx, lx); split2(v[j].y, hy, ly);
                split2(v[j].z, hz, lz); split2(v[j].w, hw, lw);
                int row = nxt * 32 + j * 16 + lr;
                *(uint2*)&ash[row * 72 + lc4] = make_uint2(pack_bf16(hx, hy), pack_bf16(hz, hw));
                *(uint2*)&asl[row * 72 + lc4] = make_uint2(pack_bf16(lx, ly), pack_bf16(lz, lw));
            }
        }
        cp_wait0();
        __syncthreads();
    }

    float* p = g_part + (((size_t)chunk * NB + b) * NC + ct * 64 + c0) * 64 + kc;
    wmma::store_matrix_sync(p, acc[0], 64, wmma::mem_row_major);
    wmma::store_matrix_sync(p + 8, acc[1], 64, wmma::mem_row_major);
}

// ---------------------------------------------------------------------------
// Reduce partials (fixed order), split + TRANSPOSE into g_skp[b][h][k][d].
// Vectorized: each thread reduces 4 consecutive k via float4.
// ---------------------------------------------------------------------------
__global__ void k_reduce() {
    int i = blockIdx.x * 256 + threadIdx.x;      // over 65536 float4 groups
    int idx = i * 4;
    float4 s = make_float4(0.f, 0.f, 0.f, 0.f);
    #pragma unroll
    for (int c = 0; c < NCHUNK; c++) {
        float4 p = *(const float4*)&g_part[(size_t)c * (NB * NC * NK) + idx];
        s.x += p.x; s.y += p.y; s.z += p.z; s.w += p.w;
    }
    int b = idx >> 14, rem = idx & 16383, c = rem >> 6, k0 = rem & 63;
    int h = c >> 6, d = c & 63;
    size_t ob = ((size_t)(b * NH + h) * 64) * 64 + d;   // + k*64
    float sv[4] = {s.x, s.y, s.z, s.w};
    #pragma unroll
    for (int j = 0; j < 4; j++) {
        __nv_bfloat16 hi, lo;
        split2(sv[j], hi, lo);
        size_t o = ob + (size_t)(k0 + j) * 64;
        g_skph[o] = hi;
        g_skpl[o] = lo;
    }
}

// ---------------------------------------------------------------------------
// Fused attention: q A-fragments direct from global, B via ldmatrix,
// register softmax + P-in-registers, DIRECT fragment->global writeback.
// 2 row-tiles (256 rows) per block; forced 2 CTAs/SM (regs 118).
// ---------------------------------------------------------------------------
#define TILES 2

__global__ void __launch_bounds__(256, 2) k_attn(
    const float* __restrict__ outq, const float* __restrict__ temp,
    float* __restrict__ x)
{
    extern __shared__ char smbuf[];
    __nv_bfloat16* sph = (__nv_bfloat16*)smbuf;          // 64x72  skpT [k][d]
    __nv_bfloat16* spl = sph + 64 * 72;
    __nv_bfloat16* vph = spl + 64 * 72;                  // 64x72  vpT  [m][k]
    __nv_bfloat16* vpl = vph + 64 * 72;

    int nt = blockIdx.x, h = blockIdx.y, b = blockIdx.z;
    int t = threadIdx.x, w = t >> 5, lane = t & 31;
    int gid = lane >> 2, tid = lane & 3;
    int r0 = w * 16;

    int brow = (lane & 7) + ((lane >> 4) << 3);
    int bcol8 = ((lane >> 3) & 1) * 8;

    {
        size_t base = (size_t)(b * NH + h) * 4096;
        for (int i = t; i < 512; i += 256) {
            int r = i >> 3, k8 = (i & 7) * 8;
            *(uint4*)&sph[r * 72 + k8] = *(const uint4*)&g_skph[base + r * 64 + k8];
            *(uint4*)&spl[r * 72 + k8] = *(const uint4*)&g_skpl[base + r * 64 + k8];
            *(uint4*)&vph[r * 72 + k8] = *(const uint4*)&g_vph[base + r * 64 + k8];
            *(uint4*)&vpl[r * 72 + k8] = *(const uint4*)&g_vpl[base + r * 64 + k8];
        }
    }
    float tempv = temp[h];
    __syncthreads();

    #pragma unroll 1
    for (int tile = 0; tile < TILES; tile++) {
        int rowbase = nt * (TILES * 128) + tile * 128 + r0 + gid;
        const float* qr0 = outq + ((size_t)b * NN + rowbase) * NC + h * 64;
        const float* qr8 = qr0 + 8 * NC;

        // ---- logits ----
        float acc[8][4];
        #pragma unroll
        for (int kb = 0; kb < 8; kb++)
            #pragma unroll
            for (int i = 0; i < 4; i++) acc[kb][i] = 0.f;

        #pragma unroll
        for (int dt = 0; dt < 4; dt++) {
            float2 v00 = *(const float2*)&qr0[dt * 16 + 2 * tid];
            float2 v10 = *(const float2*)&qr8[dt * 16 + 2 * tid];
            float2 v01 = *(const float2*)&qr0[dt * 16 + 2 * tid + 8];
            float2 v11 = *(const float2*)&qr8[dt * 16 + 2 * tid + 8];
            unsigned ah[4], al[4];
            {
                __nv_bfloat16 ha, la, hb, lb;
                split2(v00.x, ha, la); split2(v00.y, hb, lb);
                ah[0] = pack_bf16(ha, hb); al[0] = pack_bf16(la, lb);
                split2(v10.x, ha, la); split2(v10.y, hb, lb);
                ah[1] = pack_bf16(ha, hb); al[1] = pack_bf16(la, lb);
                split2(v01.x, ha, la); split2(v01.y, hb, lb);
                ah[2] = pack_bf16(ha, hb); al[2] = pack_bf16(la, lb);
                split2(v11.x, ha, la); split2(v11.y, hb, lb);
                ah[3] = pack_bf16(ha, hb); al[3] = pack_bf16(la, lb);
            }
            #pragma unroll
            for (int p = 0; p < 4; p++) {
                unsigned bh[4], bl[4];
                ldsm_x4(bh, &sph[(p * 16 + brow) * 72 + dt * 16 + bcol8]);
                ldsm_x4(bl, &spl[(p * 16 + brow) * 72 + dt * 16 + bcol8]);
                mma16816(acc[2 * p],     ah, bh);
                mma16816(acc[2 * p],     ah, bl);
                mma16816(acc[2 * p],     al, bh);
                mma16816(acc[2 * p + 1], ah, bh + 2);
                mma16816(acc[2 * p + 1], ah, bl + 2);
                mma16816(acc[2 * p + 1], al, bh + 2);
            }
        }

        // ---- softmax in registers ----
        #pragma unroll
        for (int kb = 0; kb < 8; kb++)
            #pragma unroll
            for (int i = 0; i < 4; i++) acc[kb][i] *= tempv;

        float mx0 = -1e30f, mx1 = -1e30f;
        #pragma unroll
        for (int kb = 0; kb < 8; kb++) {
            mx0 = fmaxf(mx0, fmaxf(acc[kb][0], acc[kb][1]));
            mx1 = fmaxf(mx1, fmaxf(acc[kb][2], acc[kb][3]));
        }
        mx0 = fmaxf(mx0, __shfl_xor_sync(0xffffffffu, mx0, 1));
        mx0 = fmaxf(mx0, __shfl_xor_sync(0xffffffffu, mx0, 2));
        mx1 = fmaxf(mx1, __shfl_xor_sync(0xffffffffu, mx1, 1));
        mx1 = fmaxf(mx1, __shfl_xor_sync(0xffffffffu, mx1, 2));

        float sum0 = 0.f, sum1 = 0.f;
        #pragma unroll
        for (int kb = 0; kb < 8; kb++) {
            acc[kb][0] = __expf(acc[kb][0] - mx0);
            acc[kb][1] = __expf(acc[kb][1] - mx0);
            acc[kb][2] = __expf(acc[kb][2] - mx1);
            acc[kb][3] = __expf(acc[kb][3] - mx1);
            sum0 += acc[kb][0] + acc[kb][1];
            sum1 += acc[kb][2] + acc[kb][3];
        }
        sum0 += __shfl_xor_sync(0xffffffffu, sum0, 1);
        sum0 += __shfl_xor_sync(0xffffffffu, sum0, 2);
        sum1 += __shfl_xor_sync(0xffffffffu, sum1, 1);
        sum1 += __shfl_xor_sync(0xffffffffu, sum1, 2);
        float inv0 = 1.f / sum0, inv1 = 1.f / sum1;

        // ---- pack P into bf16x3 A-fragments ----
        unsigned pah[4][4], pal[4][4];
        #pragma unroll
        for (int kt = 0; kt < 4; kt++) {
            #pragma unroll
            for (int half = 0; half < 2; half++) {
                int kb = 2 * kt + half;
                float p0 = acc[kb][0] * inv0, p1 = acc[kb][1] * inv0;
                float p2 = acc[kb][2] * inv1, p3 = acc[kb][3] * inv1;
                __nv_bfloat16 h0, l0, h1, l1, h2, l2, h3, l3;
                split2(p0, h0, l0); split2(p1, h1, l1);
                split2(p2, h2, l2); split2(p3, h3, l3);
                pah[kt][half * 2]     = pack_bf16(h0, h1);
                pah[kt][half * 2 + 1] = pack_bf16(h2, h3);
                pal[kt][half * 2]     = pack_bf16(l0, l1);
                pal[kt][half * 2 + 1] = pack_bf16(l2, l3);
            }
        }

        // ---- values ----
        float acc2[8][4];
        #pragma unroll
        for (int mb = 0; mb < 8; mb++)
            #pragma unroll
            for (int i = 0; i < 4; i++) acc2[mb][i] = 0.f;

        #pragma unroll
        for (int kt = 0; kt < 4; kt++) {
            #pragma unroll
            for (int p = 0; p < 4; p++) {
                unsigned bh[4], bl[4];
                ldsm_x4(bh, &vph[(p * 16 + brow) * 72 + kt * 16 + bcol8]);
                ldsm_x4(bl, &vpl[(p * 16 + brow) * 72 + kt * 16 + bcol8]);
                mma16816(acc2[2 * p],     pah[kt], bh);
                mma16816(acc2[2 * p],     pah[kt], bl);
                mma16816(acc2[2 * p],     pal[kt], bh);
                mma16816(acc2[2 * p + 1], pah[kt], bh + 2);
                mma16816(acc2[2 * p + 1], pah[kt], bl + 2);
                mma16816(acc2[2 * p + 1], pal[kt], bh + 2);
            }
        }

        // ---- direct writeback: x[b, m*(H*N) + h*N + n] ----
        // Fragment (mb,i) -> m = mb*8 + 2*tid + (i&1), n = rowbase + (i>>1)*8.
        // Per warp-store: 4 m-columns x 8 consecutive n = 4 full 32B sectors.
        {
            const size_t MS = (size_t)NH * NN;  // m stride
            float* od = x + (size_t)b * (NN * NC) + (size_t)h * NN + rowbase;
            #pragma unroll
            for (int mb = 0; mb < 8; mb++) {
                size_t m0 = (size_t)(mb * 8 + 2 * tid);
                od[m0 * MS]           = acc2[mb][0];
                od[(m0 + 1) * MS]     = acc2[mb][1];
                od[m0 * MS + 8]       = acc2[mb][2];
                od[(m0 + 1) * MS + 8] = acc2[mb][3];
            }
        }
    }
}

// ---------------------------------------------------------------------------
extern "C" void kernel_launch(void* const* d_in, const int* in_sizes, int n_in,
                              void* d_out, int out_size) {
    const float* skip = (const float*)d_in[0];
    const float* outq = (const float*)d_in[1];
    const float* gf   = (const float*)d_in[2];
    const float* ef1  = (const float*)d_in[3];
    const float* ef2  = (const float*)d_in[4];
    const float* temp = (const float*)d_in[5];
    float* x = (float*)d_out;

    const int ATTN_SMEM = 4 * 64 * 72 * 2;                    // 36864
    const int SKP_SMEM  = 4 * 2 * 32 * 72 * 2;                // 36864

    cudaFuncSetAttribute(k_attn, cudaFuncAttributeMaxDynamicSharedMemorySize, ATTN_SMEM);
    cudaFuncSetAttribute(k_skp,  cudaFuncAttributeMaxDynamicSharedMemorySize, SKP_SMEM);

    k_prep_ef2<<<(NN * NK) / 1024, 256>>>(ef2);
    k_gvp<<<NB * NH, 256>>>(gf, ef1);
    k_skp<<<dim3(NCHUNK, 4, NB), 256, SKP_SMEM>>>(skip);
    k_reduce<<<(NB * NC * NK) / 1024, 256>>>();
    k_attn<<<dim3(NN / (TILES * 128), NH, NB), 256, ATTN_SMEM>>>(outq, temp, x);
}